// round 14
// baseline (speedup 1.0000x reference)
#include <cuda_runtime.h>
#include <cuda_bf16.h>
#include <cuda_fp16.h>
#include <cstdint>

#define BATCH 16
#define SEQ   2048
#define DIM   128
#define BM    128
#define BN    64
#define KTILES (SEQ / BN)
#define QT_PER (SEQ / BM)          // 16
#define SPLITS 4
#define KT_LOCAL (KTILES / SPLITS) // 8
#define NTHREADS 256

// Pre-converted K/V tiles: per (b,kt) 48 KB: [K_HI 16K][K_LO 16K][V_F16 16K]
#define KV_TILE_BYTES 49152
__device__ unsigned char g_kv[(size_t)BATCH * KTILES * KV_TILE_BYTES];        // 24 MB
// Pre-converted Q tiles: per (b,qt) 64 KB: [Q_HI 32K][Q_LO 32K], swizzled
__device__ unsigned char g_qc[(size_t)BATCH * QT_PER * 65536];                // 16 MB
// Split-K partials: unnormalized O + (m,l) per row
__device__ float  g_part[(size_t)BATCH * QT_PER * SPLITS * BM * DIM];         // 64 MB
__device__ float2 g_ml[BATCH * QT_PER * SPLITS * BM];                         // 1 MB
__device__ unsigned int g_cnt[BATCH * QT_PER];                                // tickets (zero-init)

#define OFF_V   32768

// SMEM: K double-buffer (32 KB), V double-buffer (16 KB), Q hi/lo (64 KB)
#define SM_K(s)   ((s) * 32768)
#define SM_V(s)   (65536 + (s) * 16384)
#define SM_QHI    98304
#define SM_QLO    131072
#define SM_TOTAL  163840

__device__ __forceinline__ uint32_t smem_u32(const void* p) {
    uint32_t a;
    asm("{ .reg .u64 t; cvta.to.shared.u64 t, %1; cvt.u32.u64 %0, t; }" : "=r"(a) : "l"(p));
    return a;
}
__device__ __forceinline__ uint32_t swz(int r, int c4) {
    return (uint32_t)(r * 256 + ((((c4 >> 1) ^ (r & 7)) << 4) | ((c4 & 1) << 3)));
}
__device__ __forceinline__ void ldsm_x4(uint32_t* r, uint32_t a) {
    asm volatile("ldmatrix.sync.aligned.m8n8.x4.shared.b16 {%0,%1,%2,%3}, [%4];"
        : "=r"(r[0]), "=r"(r[1]), "=r"(r[2]), "=r"(r[3]) : "r"(a));
}
__device__ __forceinline__ void ldsm_x4_t(uint32_t* r, uint32_t a) {
    asm volatile("ldmatrix.sync.aligned.m8n8.x4.trans.shared.b16 {%0,%1,%2,%3}, [%4];"
        : "=r"(r[0]), "=r"(r[1]), "=r"(r[2]), "=r"(r[3]) : "r"(a));
}
__device__ __forceinline__ void mma_bf16(float* c, const uint32_t* a, uint32_t b0, uint32_t b1) {
    asm volatile("mma.sync.aligned.m16n8k16.row.col.f32.bf16.bf16.f32 "
        "{%0,%1,%2,%3}, {%4,%5,%6,%7}, {%8,%9}, {%0,%1,%2,%3};"
        : "+f"(c[0]), "+f"(c[1]), "+f"(c[2]), "+f"(c[3])
        : "r"(a[0]), "r"(a[1]), "r"(a[2]), "r"(a[3]), "r"(b0), "r"(b1));
}
__device__ __forceinline__ void mma_f16(float* c, const uint32_t* a, uint32_t b0, uint32_t b1) {
    asm volatile("mma.sync.aligned.m16n8k16.row.col.f32.f16.f16.f32 "
        "{%0,%1,%2,%3}, {%4,%5,%6,%7}, {%8,%9}, {%0,%1,%2,%3};"
        : "+f"(c[0]), "+f"(c[1]), "+f"(c[2]), "+f"(c[3])
        : "r"(a[0]), "r"(a[1]), "r"(a[2]), "r"(a[3]), "r"(b0), "r"(b1));
}
__device__ __forceinline__ void cvt_split(float4 v, uint2& hi, uint2& lo) {
    __nv_bfloat162 h01 = __floats2bfloat162_rn(v.x, v.y);
    __nv_bfloat162 h23 = __floats2bfloat162_rn(v.z, v.w);
    float rx = v.x - __bfloat162float(h01.x);
    float ry = v.y - __bfloat162float(h01.y);
    float rz = v.z - __bfloat162float(h23.x);
    float rw = v.w - __bfloat162float(h23.y);
    __nv_bfloat162 l01 = __floats2bfloat162_rn(rx, ry);
    __nv_bfloat162 l23 = __floats2bfloat162_rn(rz, rw);
    hi = make_uint2(*reinterpret_cast<uint32_t*>(&h01), *reinterpret_cast<uint32_t*>(&h23));
    lo = make_uint2(*reinterpret_cast<uint32_t*>(&l01), *reinterpret_cast<uint32_t*>(&l23));
}
__device__ __forceinline__ float ex2f(float x) {
    float y;
    asm("ex2.approx.ftz.f32 %0, %1;" : "=f"(y) : "f"(x));
    return y;
}
__device__ __forceinline__ uint32_t pack_f16(float a, float b) {
    __half2 h = __floats2half2_rn(a, b);
    return *reinterpret_cast<uint32_t*>(&h);
}
__device__ __forceinline__ void cp_async16(uint32_t dst, const void* src) {
    asm volatile("cp.async.ca.shared.global [%0], [%1], 16;" :: "r"(dst), "l"(src));
}

// ---------------- pre-pass: K/V and Q -> converted swizzled tiles ----------------
__global__ __launch_bounds__(256)
void kv_prepass(const float* __restrict__ Q, const float* __restrict__ K,
                const float* __restrict__ V)
{
    int i = blockIdx.x * 256 + threadIdx.x;
    int b   = i >> 16;
    int rem = i & 65535;
    int rg  = rem >> 5;
    int c4  = rem & 31;

    size_t src = ((size_t)b * SEQ + rg) * DIM + c4 * 4;
    uint2 hi, lo;

    // K/V: 64-row tiles
    {
        int kt = rg >> 6, r = rg & 63;
        float4 kv = *(const float4*)(K + src);
        float4 vv = *(const float4*)(V + src);
        unsigned char* dst = g_kv + (size_t)(b * KTILES + kt) * KV_TILE_BYTES;
        uint32_t so = swz(r, c4);
        cvt_split(kv, hi, lo);
        *(uint2*)(dst + 0     + so) = hi;
        *(uint2*)(dst + 16384 + so) = lo;
        uint2 vf;
        vf.x = pack_f16(vv.x, vv.y);
        vf.y = pack_f16(vv.z, vv.w);
        *(uint2*)(dst + OFF_V + so) = vf;
    }
    // Q: 128-row tiles
    {
        int qt = rg >> 7, r = rg & 127;
        float4 qv = *(const float4*)(Q + src);
        unsigned char* dst = g_qc + (size_t)(b * QT_PER + qt) * 65536;
        uint32_t so = swz(r, c4);
        cvt_split(qv, hi, lo);
        *(uint2*)(dst + so)         = hi;
        *(uint2*)(dst + 32768 + so) = lo;
    }
}

// ---------------- main kernel: one CTA = (b, qt, split); last CTA merges ----------------
__global__ __launch_bounds__(NTHREADS, 1)
void attn_mma_kernel(const float* __restrict__ scale, float* __restrict__ Out)
{
    extern __shared__ char smem[];
    const uint32_t sb = smem_u32(smem);
    __shared__ float wsh[SPLITS][BM];
    __shared__ unsigned int tick_sh;

    const int tid  = threadIdx.x;
    const int wid  = tid >> 5;
    const int lane = tid & 31;
    const int g    = lane >> 2;
    const int t4   = lane & 3;
    const int wr   = wid * 16;
    const int qt   = blockIdx.x >> 2;
    const int split= blockIdx.x & 3;
    const int q0   = qt * BM;
    const int b    = blockIdx.y;
    const int kt0  = split * KT_LOCAL;
    const int m7   = lane & 7;
    const float L2E = 1.4426950408889634f;

    const unsigned char* gkv = g_kv + (size_t)b * KTILES * KV_TILE_BYTES;
    const unsigned char* gq  = g_qc + (size_t)(b * QT_PER + qt) * 65536;

    // ---- prologue: one group = Q blob + K(kt0) + V(kt0) ----
    {
        const unsigned char* kb = gkv + (size_t)kt0 * KV_TILE_BYTES;
        #pragma unroll
        for (int u = 0; u < 16; u++) {
            int idx = tid + u * NTHREADS;
            cp_async16(sb + SM_QHI + idx * 16, gq + idx * 16);
        }
        #pragma unroll
        for (int u = 0; u < 8; u++) {
            int idx = tid + u * NTHREADS;
            cp_async16(sb + SM_K(0) + idx * 16, kb + idx * 16);
        }
        #pragma unroll
        for (int u = 0; u < 4; u++) {
            int idx = tid + u * NTHREADS;
            cp_async16(sb + SM_V(0) + idx * 16, kb + OFF_V + idx * 16);
        }
        asm volatile("cp.async.commit_group;" ::: "memory");
    }

    const uint32_t hcA = (lane >> 4) & 1;
    const uint32_t hcB = (lane >> 3) & 1;
    const uint32_t hcV = (lane >> 4) & 1;
    const uint32_t qrow  = (uint32_t)(wr + m7 + ((lane >> 3) & 1) * 8);
    const uint32_t krowl = (uint32_t)(m7 + ((lane >> 4) & 1) * 8);
    const uint32_t vrowl = (uint32_t)(lane & 15);
    const uint32_t qbase = sb + SM_QHI + qrow * 256;

    const float* sp0 = scale + (size_t)(q0 + wr + g) * SEQ + 2 * t4;
    const float* sp1 = sp0 + 8 * SEQ;

    float o[16][4];
    #pragma unroll
    for (int j = 0; j < 16; j++)
        { o[j][0] = 0.f; o[j][1] = 0.f; o[j][2] = 0.f; o[j][3] = 0.f; }
    float m0 = -1e30f, m1 = -1e30f, l0 = 0.f, l1 = 0.f;

    for (int k = 0; k < KT_LOCAL; k++) {
        const int kt = kt0 + k;
        __syncthreads();

        if (k + 1 < KT_LOCAL) {
            const unsigned char* srcb = gkv + (size_t)(kt + 1) * KV_TILE_BYTES;
            uint32_t kd = sb + SM_K((k + 1) & 1);
            #pragma unroll
            for (int u = 0; u < 8; u++) {
                int idx = tid + u * NTHREADS;
                cp_async16(kd + idx * 16, srcb + idx * 16);
            }
            uint32_t vd = sb + SM_V((k + 1) & 1);
            #pragma unroll
            for (int u = 0; u < 4; u++) {
                int idx = tid + u * NTHREADS;
                cp_async16(vd + idx * 16, srcb + OFF_V + idx * 16);
            }
            asm volatile("cp.async.commit_group;" ::: "memory");
            asm volatile("cp.async.wait_group 1;" ::: "memory");
        } else {
            asm volatile("cp.async.wait_group 0;" ::: "memory");
        }
        __syncthreads();

        const uint32_t kbase = sb + SM_K(k & 1) + krowl * 256;
        const uint32_t vbase = sb + SM_V(k & 1) + vrowl * 256;

        float2 scA[8], scB[8];
        #pragma unroll
        for (int j = 0; j < 8; j++) {
            float2 a = __ldg((const float2*)(sp0 + (size_t)kt * BN + 8 * j));
            float2 c = __ldg((const float2*)(sp1 + (size_t)kt * BN + 8 * j));
            scA[j] = make_float2(a.x * L2E, a.y * L2E);
            scB[j] = make_float2(c.x * L2E, c.y * L2E);
        }

        // ---- S = Q K^T : bf16 3-product split; half-kc batches ----
        float s[8][4];
        #pragma unroll
        for (int j = 0; j < 8; j++)
            { s[j][0] = 0.f; s[j][1] = 0.f; s[j][2] = 0.f; s[j][3] = 0.f; }

        #pragma unroll
        for (int kc = 0; kc < 8; kc++) {
            uint32_t aoff = ((2u * kc + hcA) ^ m7) << 4;
            uint32_t boff = ((2u * kc + hcB) ^ m7) << 4;
            uint32_t ah[4], al[4];
            ldsm_x4(ah, qbase + aoff);
            ldsm_x4(al, qbase + 32768 + aoff);
            {   // jp0, jp1
                uint32_t bh0[4], bl0[4], bh1[4], bl1[4];
                ldsm_x4(bh0, kbase + boff);
                ldsm_x4(bl0, kbase + 16384 + boff);
                ldsm_x4(bh1, kbase + 4096 + boff);
                ldsm_x4(bl1, kbase + 4096 + 16384 + boff);
                mma_bf16(s[0], ah, bh0[0], bh0[1]);
                mma_bf16(s[1], ah, bh0[2], bh0[3]);
                mma_bf16(s[2], ah, bh1[0], bh1[1]);
                mma_bf16(s[3], ah, bh1[2], bh1[3]);
                mma_bf16(s[0], ah, bl0[0], bl0[1]);
                mma_bf16(s[1], ah, bl0[2], bl0[3]);
                mma_bf16(s[2], ah, bl1[0], bl1[1]);
                mma_bf16(s[3], ah, bl1[2], bl1[3]);
                mma_bf16(s[0], al, bh0[0], bh0[1]);
                mma_bf16(s[1], al, bh0[2], bh0[3]);
                mma_bf16(s[2], al, bh1[0], bh1[1]);
                mma_bf16(s[3], al, bh1[2], bh1[3]);
            }
            {   // jp2, jp3
                uint32_t bh2[4], bl2[4], bh3[4], bl3[4];
                ldsm_x4(bh2, kbase + 2 * 4096 + boff);
                ldsm_x4(bl2, kbase + 2 * 4096 + 16384 + boff);
                ldsm_x4(bh3, kbase + 3 * 4096 + boff);
                ldsm_x4(bl3, kbase + 3 * 4096 + 16384 + boff);
                mma_bf16(s[4], ah, bh2[0], bh2[1]);
                mma_bf16(s[5], ah, bh2[2], bh2[3]);
                mma_bf16(s[6], ah, bh3[0], bh3[1]);
                mma_bf16(s[7], ah, bh3[2], bh3[3]);
                mma_bf16(s[4], ah, bl2[0], bl2[1]);
                mma_bf16(s[5], ah, bl2[2], bl2[3]);
                mma_bf16(s[6], ah, bl3[0], bl3[1]);
                mma_bf16(s[7], ah, bl3[2], bl3[3]);
                mma_bf16(s[4], al, bh2[0], bh2[1]);
                mma_bf16(s[5], al, bh2[2], bh2[3]);
                mma_bf16(s[6], al, bh3[0], bh3[1]);
                mma_bf16(s[7], al, bh3[2], bh3[3]);
            }
        }

        // ---- softmax ----
        float mx0 = -1e30f, mx1 = -1e30f;
        #pragma unroll
        for (int j = 0; j < 8; j++) {
            s[j][0] *= scA[j].x; s[j][1] *= scA[j].y;
            s[j][2] *= scB[j].x; s[j][3] *= scB[j].y;
            mx0 = fmaxf(mx0, fmaxf(s[j][0], s[j][1]));
            mx1 = fmaxf(mx1, fmaxf(s[j][2], s[j][3]));
        }
        mx0 = fmaxf(mx0, __shfl_xor_sync(0xffffffffu, mx0, 1));
        mx0 = fmaxf(mx0, __shfl_xor_sync(0xffffffffu, mx0, 2));
        mx1 = fmaxf(mx1, __shfl_xor_sync(0xffffffffu, mx1, 1));
        mx1 = fmaxf(mx1, __shfl_xor_sync(0xffffffffu, mx1, 2));

        float mn0 = fmaxf(m0, mx0), mn1 = fmaxf(m1, mx1);
        float a0 = ex2f(m0 - mn0),  a1 = ex2f(m1 - mn1);
        m0 = mn0; m1 = mn1;
        if (a0 != 1.0f || a1 != 1.0f) {
            l0 *= a0; l1 *= a1;
            #pragma unroll
            for (int j = 0; j < 16; j++) {
                o[j][0] *= a0; o[j][1] *= a0;
                o[j][2] *= a1; o[j][3] *= a1;
            }
        }

        // ---- exp + pack + PV per key-chunk ----
        float sum0 = 0.f, sum1 = 0.f;
        #pragma unroll
        for (int c = 0; c < 4; c++) {
            float e00 = ex2f(s[2*c][0]   - mn0), e01 = ex2f(s[2*c][1]   - mn0);
            float e02 = ex2f(s[2*c][2]   - mn1), e03 = ex2f(s[2*c][3]   - mn1);
            float e10 = ex2f(s[2*c+1][0] - mn0), e11 = ex2f(s[2*c+1][1] - mn0);
            float e12 = ex2f(s[2*c+1][2] - mn1), e13 = ex2f(s[2*c+1][3] - mn1);
            sum0 += e00 + e01 + e10 + e11;
            sum1 += e02 + e03 + e12 + e13;
            uint32_t ph[4];
            ph[0] = pack_f16(e00, e01);
            ph[1] = pack_f16(e02, e03);
            ph[2] = pack_f16(e10, e11);
            ph[3] = pack_f16(e12, e13);
            #pragma unroll
            for (int half = 0; half < 2; half++) {
                uint32_t vh[4][4];
                #pragma unroll
                for (int q = 0; q < 4; q++) {
                    int jp = 4 * half + q;
                    uint32_t va = vbase + c * 4096u + (((2u * jp + hcV) ^ m7) << 4);
                    ldsm_x4_t(vh[q], va);
                }
                #pragma unroll
                for (int q = 0; q < 4; q++) {
                    int jp = 4 * half + q;
                    mma_f16(o[2*jp],   ph, vh[q][0], vh[q][1]);
                    mma_f16(o[2*jp+1], ph, vh[q][2], vh[q][3]);
                }
            }
        }
        l0 += sum0; l1 += sum1;
    }

    // ---- write unnormalized partials + (m,l) ----
    l0 += __shfl_xor_sync(0xffffffffu, l0, 1);
    l0 += __shfl_xor_sync(0xffffffffu, l0, 2);
    l1 += __shfl_xor_sync(0xffffffffu, l1, 1);
    l1 += __shfl_xor_sync(0xffffffffu, l1, 2);

    const int bq = b * QT_PER + qt;
    const int p  = bq * SPLITS + split;
    float* po = g_part + (size_t)p * BM * DIM;
    const int row0 = wr + g, row1 = row0 + 8;
    #pragma unroll
    for (int j = 0; j < 16; j++) {
        int col = 8 * j + 2 * t4;
        *(float2*)(po + row0 * DIM + col) = make_float2(o[j][0], o[j][1]);
        *(float2*)(po + row1 * DIM + col) = make_float2(o[j][2], o[j][3]);
    }
    if (t4 == 0) {
        g_ml[p * BM + row0] = make_float2(m0, l0);
        g_ml[p * BM + row1] = make_float2(m1, l1);
    }

    // ---- ticket: last CTA of this (b,qt) group merges ----
    __threadfence();
    __syncthreads();
    if (tid == 0) tick_sh = atomicAdd(&g_cnt[bq], 1u);
    __syncthreads();
    if (tick_sh == SPLITS - 1) {
        if (tid < BM) {
            float2 ml[SPLITS];
            float M = -1e30f;
            #pragma unroll
            for (int sI = 0; sI < SPLITS; sI++) {
                ml[sI] = g_ml[(bq * SPLITS + sI) * BM + tid];
                M = fmaxf(M, ml[sI].x);
            }
            float w[SPLITS], L = 0.f;
            #pragma unroll
            for (int sI = 0; sI < SPLITS; sI++) {
                w[sI] = ex2f(ml[sI].x - M);      // m is in log2 domain
                L += ml[sI].y * w[sI];
            }
            float inv = 1.f / L;
            #pragma unroll
            for (int sI = 0; sI < SPLITS; sI++) wsh[sI][tid] = w[sI] * inv;
        }
        __syncthreads();

        const float* p0 = g_part + (size_t)bq * SPLITS * BM * DIM;
        float* out = Out + (size_t)bq * BM * DIM;
        for (int e4 = tid; e4 < BM * DIM / 4; e4 += NTHREADS) {
            int e = e4 * 4;
            int row = e >> 7;
            float4 v0 = *(const float4*)(p0 + e);
            float4 v1 = *(const float4*)(p0 + BM * DIM + e);
            float4 v2 = *(const float4*)(p0 + 2 * BM * DIM + e);
            float4 v3 = *(const float4*)(p0 + 3 * BM * DIM + e);
            float w0 = wsh[0][row], w1 = wsh[1][row], w2 = wsh[2][row], w3 = wsh[3][row];
            float4 r;
            r.x = v0.x * w0 + v1.x * w1 + v2.x * w2 + v3.x * w3;
            r.y = v0.y * w0 + v1.y * w1 + v2.y * w2 + v3.y * w3;
            r.z = v0.z * w0 + v1.z * w1 + v2.z * w2 + v3.z * w3;
            r.w = v0.w * w0 + v1.w * w1 + v2.w * w2 + v3.w * w3;
            *(float4*)(out + e) = r;
        }
        __syncthreads();
        if (tid == 0) g_cnt[bq] = 0;            // reset for next graph replay
    }
}

extern "C" void kernel_launch(void* const* d_in, const int* in_sizes, int n_in,
                              void* d_out, int out_size)
{
    const float* Q     = (const float*)d_in[0];
    const float* K     = (const float*)d_in[1];
    const float* V     = (const float*)d_in[2];
    const float* scale = (const float*)d_in[3];
    float* O = (float*)d_out;

    kv_prepass<<<(BATCH * SEQ * 32) / 256, 256>>>(Q, K, V);

    cudaFuncSetAttribute(attn_mma_kernel,
                         cudaFuncAttributeMaxDynamicSharedMemorySize, SM_TOTAL);
    dim3 grid(QT_PER * SPLITS, BATCH);   // 64 x 16 = 1024 CTAs
    attn_mma_kernel<<<grid, NTHREADS, SM_TOTAL>>>(scale, O);
}

// round 15
// speedup vs baseline: 1.0423x; 1.0423x over previous
#include <cuda_runtime.h>
#include <cuda_bf16.h>
#include <cuda_fp16.h>
#include <cstdint>

#define BATCH 16
#define SEQ   2048
#define DIM   128
#define BM    128
#define BN    64
#define KTILES (SEQ / BN)
#define QT_PER (SEQ / BM)          // 16
#define SPLITS 4
#define KT_LOCAL (KTILES / SPLITS) // 8
#define NTHREADS 256

// Pre-converted K/V tiles: per (b,kt) 48 KB: [K_HI 16K][K_LO 16K][V_F16 16K]
#define KV_TILE_BYTES 49152
__device__ unsigned char g_kv[(size_t)BATCH * KTILES * KV_TILE_BYTES];        // 24 MB
// Pre-converted Q tiles: per (b,qt) 64 KB: [Q_HI 32K][Q_LO 32K], swizzled
__device__ unsigned char g_qc[(size_t)BATCH * QT_PER * 65536];                // 16 MB
// Split-K partials: unnormalized O + (m,l) per row
__device__ float  g_part[(size_t)BATCH * QT_PER * SPLITS * BM * DIM];         // 64 MB
__device__ float2 g_ml[BATCH * QT_PER * SPLITS * BM];                         // 1 MB

#define OFF_V   32768

// SMEM: K double-buffer (32 KB), V double-buffer (16 KB), Q hi/lo (64 KB)
#define SM_K(s)   ((s) * 32768)
#define SM_V(s)   (65536 + (s) * 16384)
#define SM_QHI    98304
#define SM_QLO    131072
#define SM_TOTAL  163840

__device__ __forceinline__ uint32_t smem_u32(const void* p) {
    uint32_t a;
    asm("{ .reg .u64 t; cvta.to.shared.u64 t, %1; cvt.u32.u64 %0, t; }" : "=r"(a) : "l"(p));
    return a;
}
__device__ __forceinline__ uint32_t swz(int r, int c4) {
    return (uint32_t)(r * 256 + ((((c4 >> 1) ^ (r & 7)) << 4) | ((c4 & 1) << 3)));
}
__device__ __forceinline__ void ldsm_x4(uint32_t* r, uint32_t a) {
    asm volatile("ldmatrix.sync.aligned.m8n8.x4.shared.b16 {%0,%1,%2,%3}, [%4];"
        : "=r"(r[0]), "=r"(r[1]), "=r"(r[2]), "=r"(r[3]) : "r"(a));
}
__device__ __forceinline__ void ldsm_x4_t(uint32_t* r, uint32_t a) {
    asm volatile("ldmatrix.sync.aligned.m8n8.x4.trans.shared.b16 {%0,%1,%2,%3}, [%4];"
        : "=r"(r[0]), "=r"(r[1]), "=r"(r[2]), "=r"(r[3]) : "r"(a));
}
__device__ __forceinline__ void mma_bf16(float* c, const uint32_t* a, uint32_t b0, uint32_t b1) {
    asm volatile("mma.sync.aligned.m16n8k16.row.col.f32.bf16.bf16.f32 "
        "{%0,%1,%2,%3}, {%4,%5,%6,%7}, {%8,%9}, {%0,%1,%2,%3};"
        : "+f"(c[0]), "+f"(c[1]), "+f"(c[2]), "+f"(c[3])
        : "r"(a[0]), "r"(a[1]), "r"(a[2]), "r"(a[3]), "r"(b0), "r"(b1));
}
__device__ __forceinline__ void mma_f16(float* c, const uint32_t* a, uint32_t b0, uint32_t b1) {
    asm volatile("mma.sync.aligned.m16n8k16.row.col.f32.f16.f16.f32 "
        "{%0,%1,%2,%3}, {%4,%5,%6,%7}, {%8,%9}, {%0,%1,%2,%3};"
        : "+f"(c[0]), "+f"(c[1]), "+f"(c[2]), "+f"(c[3])
        : "r"(a[0]), "r"(a[1]), "r"(a[2]), "r"(a[3]), "r"(b0), "r"(b1));
}
__device__ __forceinline__ void cvt_split(float4 v, uint2& hi, uint2& lo) {
    __nv_bfloat162 h01 = __floats2bfloat162_rn(v.x, v.y);
    __nv_bfloat162 h23 = __floats2bfloat162_rn(v.z, v.w);
    float rx = v.x - __bfloat162float(h01.x);
    float ry = v.y - __bfloat162float(h01.y);
    float rz = v.z - __bfloat162float(h23.x);
    float rw = v.w - __bfloat162float(h23.y);
    __nv_bfloat162 l01 = __floats2bfloat162_rn(rx, ry);
    __nv_bfloat162 l23 = __floats2bfloat162_rn(rz, rw);
    hi = make_uint2(*reinterpret_cast<uint32_t*>(&h01), *reinterpret_cast<uint32_t*>(&h23));
    lo = make_uint2(*reinterpret_cast<uint32_t*>(&l01), *reinterpret_cast<uint32_t*>(&l23));
}
__device__ __forceinline__ float ex2f(float x) {
    float y;
    asm("ex2.approx.ftz.f32 %0, %1;" : "=f"(y) : "f"(x));
    return y;
}
__device__ __forceinline__ uint32_t pack_f16(float a, float b) {
    __half2 h = __floats2half2_rn(a, b);
    return *reinterpret_cast<uint32_t*>(&h);
}
__device__ __forceinline__ void cp_async16(uint32_t dst, const void* src) {
    asm volatile("cp.async.ca.shared.global [%0], [%1], 16;" :: "r"(dst), "l"(src));
}

// ---------------- pre-pass: K/V and Q -> converted swizzled tiles ----------------
// One thread handles two adjacent 16B chunks (c4, c4+1) for higher MLP.
__global__ __launch_bounds__(256)
void kv_prepass(const float* __restrict__ Q, const float* __restrict__ K,
                const float* __restrict__ V)
{
    int i = blockIdx.x * 256 + threadIdx.x;          // 0 .. BATCH*2048*16-1
    int b   = i >> 15;
    int rem = i & 32767;
    int rg  = rem >> 4;
    int c8  = rem & 15;                              // pair index: chunks 2*c8, 2*c8+1

    size_t src = ((size_t)b * SEQ + rg) * DIM + c8 * 8;
    float4 kv0 = *(const float4*)(K + src);
    float4 kv1 = *(const float4*)(K + src + 4);
    float4 vv0 = *(const float4*)(V + src);
    float4 vv1 = *(const float4*)(V + src + 4);
    float4 qv0 = *(const float4*)(Q + src);
    float4 qv1 = *(const float4*)(Q + src + 4);

    uint2 hi0, lo0, hi1, lo1;

    // K/V: 64-row tiles
    {
        int kt = rg >> 6, r = rg & 63;
        unsigned char* dst = g_kv + (size_t)(b * KTILES + kt) * KV_TILE_BYTES;
        uint32_t so0 = swz(r, 2 * c8);
        uint32_t so1 = swz(r, 2 * c8 + 1);
        cvt_split(kv0, hi0, lo0);
        cvt_split(kv1, hi1, lo1);
        *(uint2*)(dst + so0)         = hi0;
        *(uint2*)(dst + so1)         = hi1;
        *(uint2*)(dst + 16384 + so0) = lo0;
        *(uint2*)(dst + 16384 + so1) = lo1;
        uint2 vf0, vf1;
        vf0.x = pack_f16(vv0.x, vv0.y); vf0.y = pack_f16(vv0.z, vv0.w);
        vf1.x = pack_f16(vv1.x, vv1.y); vf1.y = pack_f16(vv1.z, vv1.w);
        *(uint2*)(dst + OFF_V + so0) = vf0;
        *(uint2*)(dst + OFF_V + so1) = vf1;
    }
    // Q: 128-row tiles
    {
        int qt = rg >> 7, r = rg & 127;
        unsigned char* dst = g_qc + (size_t)(b * QT_PER + qt) * 65536;
        uint32_t so0 = swz(r, 2 * c8);
        uint32_t so1 = swz(r, 2 * c8 + 1);
        cvt_split(qv0, hi0, lo0);
        cvt_split(qv1, hi1, lo1);
        *(uint2*)(dst + so0)         = hi0;
        *(uint2*)(dst + so1)         = hi1;
        *(uint2*)(dst + 32768 + so0) = lo0;
        *(uint2*)(dst + 32768 + so1) = lo1;
    }
}

// ---------------- main kernel: one CTA = (b, qt, split of 8 ktiles) ----------------
__global__ __launch_bounds__(NTHREADS, 1)
void attn_mma_kernel(const float* __restrict__ scale)
{
    extern __shared__ char smem[];
    const uint32_t sb = smem_u32(smem);

    const int tid  = threadIdx.x;
    const int wid  = tid >> 5;
    const int lane = tid & 31;
    const int g    = lane >> 2;
    const int t4   = lane & 3;
    const int wr   = wid * 16;
    const int qt   = blockIdx.x >> 2;
    const int split= blockIdx.x & 3;
    const int q0   = qt * BM;
    const int b    = blockIdx.y;
    const int kt0  = split * KT_LOCAL;
    const int m7   = lane & 7;
    const float L2E = 1.4426950408889634f;

    const unsigned char* gkv = g_kv + (size_t)b * KTILES * KV_TILE_BYTES;
    const unsigned char* gq  = g_qc + (size_t)(b * QT_PER + qt) * 65536;

    // ---- prologue: one group = Q blob + K(kt0) + V(kt0) ----
    {
        const unsigned char* kb = gkv + (size_t)kt0 * KV_TILE_BYTES;
        #pragma unroll
        for (int u = 0; u < 16; u++) {
            int idx = tid + u * NTHREADS;
            cp_async16(sb + SM_QHI + idx * 16, gq + idx * 16);
        }
        #pragma unroll
        for (int u = 0; u < 8; u++) {
            int idx = tid + u * NTHREADS;
            cp_async16(sb + SM_K(0) + idx * 16, kb + idx * 16);
        }
        #pragma unroll
        for (int u = 0; u < 4; u++) {
            int idx = tid + u * NTHREADS;
            cp_async16(sb + SM_V(0) + idx * 16, kb + OFF_V + idx * 16);
        }
        asm volatile("cp.async.commit_group;" ::: "memory");
    }

    const uint32_t hcA = (lane >> 4) & 1;
    const uint32_t hcB = (lane >> 3) & 1;
    const uint32_t hcV = (lane >> 4) & 1;
    const uint32_t qrow  = (uint32_t)(wr + m7 + ((lane >> 3) & 1) * 8);
    const uint32_t krowl = (uint32_t)(m7 + ((lane >> 4) & 1) * 8);
    const uint32_t vrowl = (uint32_t)(lane & 15);
    const uint32_t qbase = sb + SM_QHI + qrow * 256;

    const float* sp0 = scale + (size_t)(q0 + wr + g) * SEQ + 2 * t4;
    const float* sp1 = sp0 + 8 * SEQ;

    float o[16][4];
    #pragma unroll
    for (int j = 0; j < 16; j++)
        { o[j][0] = 0.f; o[j][1] = 0.f; o[j][2] = 0.f; o[j][3] = 0.f; }
    float m0 = -1e30f, m1 = -1e30f, l0 = 0.f, l1 = 0.f;

    for (int k = 0; k < KT_LOCAL; k++) {
        const int kt = kt0 + k;
        __syncthreads();   // all warps done with tile k-1 -> its slots reusable

        if (k + 1 < KT_LOCAL) {
            const unsigned char* srcb = gkv + (size_t)(kt + 1) * KV_TILE_BYTES;
            uint32_t kd = sb + SM_K((k + 1) & 1);
            #pragma unroll
            for (int u = 0; u < 8; u++) {
                int idx = tid + u * NTHREADS;
                cp_async16(kd + idx * 16, srcb + idx * 16);
            }
            uint32_t vd = sb + SM_V((k + 1) & 1);
            #pragma unroll
            for (int u = 0; u < 4; u++) {
                int idx = tid + u * NTHREADS;
                cp_async16(vd + idx * 16, srcb + OFF_V + idx * 16);
            }
            asm volatile("cp.async.commit_group;" ::: "memory");
            asm volatile("cp.async.wait_group 1;" ::: "memory");
        } else {
            asm volatile("cp.async.wait_group 0;" ::: "memory");
        }
        __syncthreads();   // tile k staged & visible

        const uint32_t kbase = sb + SM_K(k & 1) + krowl * 256;
        const uint32_t vbase = sb + SM_V(k & 1) + vrowl * 256;

        // scale rows -> regs (L2 hits, hidden under QK), log2e folded
        float2 scA[8], scB[8];
        #pragma unroll
        for (int j = 0; j < 8; j++) {
            float2 a = __ldg((const float2*)(sp0 + (size_t)kt * BN + 8 * j));
            float2 c = __ldg((const float2*)(sp1 + (size_t)kt * BN + 8 * j));
            scA[j] = make_float2(a.x * L2E, a.y * L2E);
            scB[j] = make_float2(c.x * L2E, c.y * L2E);
        }

        // ---- S = Q K^T : bf16 3-product split; half-kc batches ----
        float s[8][4];
        #pragma unroll
        for (int j = 0; j < 8; j++)
            { s[j][0] = 0.f; s[j][1] = 0.f; s[j][2] = 0.f; s[j][3] = 0.f; }

        #pragma unroll
        for (int kc = 0; kc < 8; kc++) {
            uint32_t aoff = ((2u * kc + hcA) ^ m7) << 4;
            uint32_t boff = ((2u * kc + hcB) ^ m7) << 4;
            uint32_t ah[4], al[4];
            ldsm_x4(ah, qbase + aoff);
            ldsm_x4(al, qbase + 32768 + aoff);
            {   // jp0, jp1
                uint32_t bh0[4], bl0[4], bh1[4], bl1[4];
                ldsm_x4(bh0, kbase + boff);
                ldsm_x4(bl0, kbase + 16384 + boff);
                ldsm_x4(bh1, kbase + 4096 + boff);
                ldsm_x4(bl1, kbase + 4096 + 16384 + boff);
                mma_bf16(s[0], ah, bh0[0], bh0[1]);
                mma_bf16(s[1], ah, bh0[2], bh0[3]);
                mma_bf16(s[2], ah, bh1[0], bh1[1]);
                mma_bf16(s[3], ah, bh1[2], bh1[3]);
                mma_bf16(s[0], ah, bl0[0], bl0[1]);
                mma_bf16(s[1], ah, bl0[2], bl0[3]);
                mma_bf16(s[2], ah, bl1[0], bl1[1]);
                mma_bf16(s[3], ah, bl1[2], bl1[3]);
                mma_bf16(s[0], al, bh0[0], bh0[1]);
                mma_bf16(s[1], al, bh0[2], bh0[3]);
                mma_bf16(s[2], al, bh1[0], bh1[1]);
                mma_bf16(s[3], al, bh1[2], bh1[3]);
            }
            {   // jp2, jp3
                uint32_t bh2[4], bl2[4], bh3[4], bl3[4];
                ldsm_x4(bh2, kbase + 2 * 4096 + boff);
                ldsm_x4(bl2, kbase + 2 * 4096 + 16384 + boff);
                ldsm_x4(bh3, kbase + 3 * 4096 + boff);
                ldsm_x4(bl3, kbase + 3 * 4096 + 16384 + boff);
                mma_bf16(s[4], ah, bh2[0], bh2[1]);
                mma_bf16(s[5], ah, bh2[2], bh2[3]);
                mma_bf16(s[6], ah, bh3[0], bh3[1]);
                mma_bf16(s[7], ah, bh3[2], bh3[3]);
                mma_bf16(s[4], ah, bl2[0], bl2[1]);
                mma_bf16(s[5], ah, bl2[2], bl2[3]);
                mma_bf16(s[6], ah, bl3[0], bl3[1]);
                mma_bf16(s[7], ah, bl3[2], bl3[3]);
                mma_bf16(s[4], al, bh2[0], bh2[1]);
                mma_bf16(s[5], al, bh2[2], bh2[3]);
                mma_bf16(s[6], al, bh3[0], bh3[1]);
                mma_bf16(s[7], al, bh3[2], bh3[3]);
            }
        }

        // ---- softmax: scale (log2 domain) + row max + alpha + rescale ----
        float mx0 = -1e30f, mx1 = -1e30f;
        #pragma unroll
        for (int j = 0; j < 8; j++) {
            s[j][0] *= scA[j].x; s[j][1] *= scA[j].y;
            s[j][2] *= scB[j].x; s[j][3] *= scB[j].y;
            mx0 = fmaxf(mx0, fmaxf(s[j][0], s[j][1]));
            mx1 = fmaxf(mx1, fmaxf(s[j][2], s[j][3]));
        }
        mx0 = fmaxf(mx0, __shfl_xor_sync(0xffffffffu, mx0, 1));
        mx0 = fmaxf(mx0, __shfl_xor_sync(0xffffffffu, mx0, 2));
        mx1 = fmaxf(mx1, __shfl_xor_sync(0xffffffffu, mx1, 1));
        mx1 = fmaxf(mx1, __shfl_xor_sync(0xffffffffu, mx1, 2));

        float mn0 = fmaxf(m0, mx0), mn1 = fmaxf(m1, mx1);
        float a0 = ex2f(m0 - mn0),  a1 = ex2f(m1 - mn1);
        m0 = mn0; m1 = mn1;
        if (a0 != 1.0f || a1 != 1.0f) {
            l0 *= a0; l1 *= a1;
            #pragma unroll
            for (int j = 0; j < 16; j++) {
                o[j][0] *= a0; o[j][1] *= a0;
                o[j][2] *= a1; o[j][3] *= a1;
            }
        }

        // ---- exp + pack + PV per key-chunk ----
        float sum0 = 0.f, sum1 = 0.f;
        #pragma unroll
        for (int c = 0; c < 4; c++) {
            float e00 = ex2f(s[2*c][0]   - mn0), e01 = ex2f(s[2*c][1]   - mn0);
            float e02 = ex2f(s[2*c][2]   - mn1), e03 = ex2f(s[2*c][3]   - mn1);
            float e10 = ex2f(s[2*c+1][0] - mn0), e11 = ex2f(s[2*c+1][1] - mn0);
            float e12 = ex2f(s[2*c+1][2] - mn1), e13 = ex2f(s[2*c+1][3] - mn1);
            sum0 += e00 + e01 + e10 + e11;
            sum1 += e02 + e03 + e12 + e13;
            uint32_t ph[4];
            ph[0] = pack_f16(e00, e01);
            ph[1] = pack_f16(e02, e03);
            ph[2] = pack_f16(e10, e11);
            ph[3] = pack_f16(e12, e13);
            #pragma unroll
            for (int half = 0; half < 2; half++) {
                uint32_t vh[4][4];
                #pragma unroll
                for (int q = 0; q < 4; q++) {
                    int jp = 4 * half + q;
                    uint32_t va = vbase + c * 4096u + (((2u * jp + hcV) ^ m7) << 4);
                    ldsm_x4_t(vh[q], va);
                }
                #pragma unroll
                for (int q = 0; q < 4; q++) {
                    int jp = 4 * half + q;
                    mma_f16(o[2*jp],   ph, vh[q][0], vh[q][1]);
                    mma_f16(o[2*jp+1], ph, vh[q][2], vh[q][3]);
                }
            }
        }
        l0 += sum0; l1 += sum1;
    }

    // ---- epilogue: quad-reduce l, write unnormalized partials + (m,l) ----
    l0 += __shfl_xor_sync(0xffffffffu, l0, 1);
    l0 += __shfl_xor_sync(0xffffffffu, l0, 2);
    l1 += __shfl_xor_sync(0xffffffffu, l1, 1);
    l1 += __shfl_xor_sync(0xffffffffu, l1, 2);

    const int p = (b * QT_PER + qt) * SPLITS + split;
    float* po = g_part + (size_t)p * BM * DIM;
    const int row0 = wr + g, row1 = row0 + 8;
    #pragma unroll
    for (int j = 0; j < 16; j++) {
        int col = 8 * j + 2 * t4;
        *(float2*)(po + row0 * DIM + col) = make_float2(o[j][0], o[j][1]);
        *(float2*)(po + row1 * DIM + col) = make_float2(o[j][2], o[j][3]);
    }
    if (t4 == 0) {
        g_ml[p * BM + row0] = make_float2(m0, l0);
        g_ml[p * BM + row1] = make_float2(m1, l1);
    }
}

// ---------------- combine: each CTA merges a 32-row slice of one (b,qt) ----------------
__global__ __launch_bounds__(256)
void combine_kernel(float* __restrict__ Out)
{
    const int bq   = blockIdx.x;             // b*QT_PER + qt
    const int qrt  = blockIdx.y;             // row slice: rows 32*qrt .. 32*qrt+31
    const int tid  = threadIdx.x;
    __shared__ float wsh[SPLITS][32];

    if (tid < 32) {
        int row = qrt * 32 + tid;
        float2 ml[SPLITS];
        float M = -1e30f;
        #pragma unroll
        for (int s = 0; s < SPLITS; s++) {
            ml[s] = g_ml[(bq * SPLITS + s) * BM + row];
            M = fmaxf(M, ml[s].x);
        }
        float w[SPLITS], L = 0.f;
        #pragma unroll
        for (int s = 0; s < SPLITS; s++) {
            w[s] = ex2f(ml[s].x - M);        // m is in log2 domain
            L += ml[s].y * w[s];
        }
        float inv = 1.f / L;
        #pragma unroll
        for (int s = 0; s < SPLITS; s++) wsh[s][tid] = w[s] * inv;
    }
    __syncthreads();

    const int base = qrt * 32 * DIM;         // slice offset in elements
    const float* p0 = g_part + (size_t)bq * SPLITS * BM * DIM + base;
    float* out = Out + (size_t)bq * BM * DIM + base;
    for (int e4 = tid; e4 < 32 * DIM / 4; e4 += 256) {
        int e = e4 * 4;
        int row = e >> 7;                    // local row in slice
        float4 v0 = __ldg((const float4*)(p0 + e));
        float4 v1 = __ldg((const float4*)(p0 + BM * DIM + e));
        float4 v2 = __ldg((const float4*)(p0 + 2 * BM * DIM + e));
        float4 v3 = __ldg((const float4*)(p0 + 3 * BM * DIM + e));
        float w0 = wsh[0][row], w1 = wsh[1][row], w2 = wsh[2][row], w3 = wsh[3][row];
        float4 r;
        r.x = v0.x * w0 + v1.x * w1 + v2.x * w2 + v3.x * w3;
        r.y = v0.y * w0 + v1.y * w1 + v2.y * w2 + v3.y * w3;
        r.z = v0.z * w0 + v1.z * w1 + v2.z * w2 + v3.z * w3;
        r.w = v0.w * w0 + v1.w * w1 + v2.w * w2 + v3.w * w3;
        *(float4*)(out + e) = r;
    }
}

extern "C" void kernel_launch(void* const* d_in, const int* in_sizes, int n_in,
                              void* d_out, int out_size)
{
    const float* Q     = (const float*)d_in[0];
    const float* K     = (const float*)d_in[1];
    const float* V     = (const float*)d_in[2];
    const float* scale = (const float*)d_in[3];
    float* O = (float*)d_out;

    kv_prepass<<<(BATCH * SEQ * 16) / 256, 256>>>(Q, K, V);

    cudaFuncSetAttribute(attn_mma_kernel,
                         cudaFuncAttributeMaxDynamicSharedMemorySize, SM_TOTAL);
    dim3 grid(QT_PER * SPLITS, BATCH);   // 64 x 16 = 1024 CTAs
    attn_mma_kernel<<<grid, NTHREADS, SM_TOTAL>>>(scale);

    dim3 cgrid(BATCH * QT_PER, SPLITS);  // 256 x 4 = 1024 light CTAs
    combine_kernel<<<cgrid, 256>>>(O);
}

// round 16
// speedup vs baseline: 1.0502x; 1.0076x over previous
#include <cuda_runtime.h>
#include <cuda_bf16.h>
#include <cuda_fp16.h>
#include <cstdint>

#define BATCH 16
#define SEQ   2048
#define DIM   128
#define BM    128
#define BN    64
#define KTILES (SEQ / BN)
#define QT_PER (SEQ / BM)          // 16
#define SPLITS 4
#define KT_LOCAL (KTILES / SPLITS) // 8
#define NTHREADS 256

// Pre-converted K/V tiles: per (b,kt) 48 KB: [K_HI 16K][K_LO 16K][V_F16 16K]
#define KV_TILE_BYTES 49152
__device__ unsigned char g_kv[(size_t)BATCH * KTILES * KV_TILE_BYTES];        // 24 MB
// Pre-converted Q tiles: per (b,qt) 64 KB: [Q_HI 32K][Q_LO 32K], swizzled
__device__ unsigned char g_qc[(size_t)BATCH * QT_PER * 65536];                // 16 MB
// Split-K partials: unnormalized O + (m,l) per row
__device__ float  g_part[(size_t)BATCH * QT_PER * SPLITS * BM * DIM];         // 64 MB
__device__ float2 g_ml[BATCH * QT_PER * SPLITS * BM];                         // 1 MB

#define OFF_V   32768

// SMEM: K double-buffer (32 KB), V double-buffer (16 KB), Q hi/lo (64 KB)
#define SM_K(s)   ((s) * 32768)
#define SM_V(s)   (65536 + (s) * 16384)
#define SM_QHI    98304
#define SM_QLO    131072
#define SM_TOTAL  163840

__device__ __forceinline__ uint32_t smem_u32(const void* p) {
    uint32_t a;
    asm("{ .reg .u64 t; cvta.to.shared.u64 t, %1; cvt.u32.u64 %0, t; }" : "=r"(a) : "l"(p));
    return a;
}
__device__ __forceinline__ uint32_t swz(int r, int c4) {
    return (uint32_t)(r * 256 + ((((c4 >> 1) ^ (r & 7)) << 4) | ((c4 & 1) << 3)));
}
__device__ __forceinline__ void ldsm_x4(uint32_t* r, uint32_t a) {
    asm volatile("ldmatrix.sync.aligned.m8n8.x4.shared.b16 {%0,%1,%2,%3}, [%4];"
        : "=r"(r[0]), "=r"(r[1]), "=r"(r[2]), "=r"(r[3]) : "r"(a));
}
__device__ __forceinline__ void ldsm_x4_t(uint32_t* r, uint32_t a) {
    asm volatile("ldmatrix.sync.aligned.m8n8.x4.trans.shared.b16 {%0,%1,%2,%3}, [%4];"
        : "=r"(r[0]), "=r"(r[1]), "=r"(r[2]), "=r"(r[3]) : "r"(a));
}
__device__ __forceinline__ void mma_bf16(float* c, const uint32_t* a, uint32_t b0, uint32_t b1) {
    asm volatile("mma.sync.aligned.m16n8k16.row.col.f32.bf16.bf16.f32 "
        "{%0,%1,%2,%3}, {%4,%5,%6,%7}, {%8,%9}, {%0,%1,%2,%3};"
        : "+f"(c[0]), "+f"(c[1]), "+f"(c[2]), "+f"(c[3])
        : "r"(a[0]), "r"(a[1]), "r"(a[2]), "r"(a[3]), "r"(b0), "r"(b1));
}
__device__ __forceinline__ void mma_f16(float* c, const uint32_t* a, uint32_t b0, uint32_t b1) {
    asm volatile("mma.sync.aligned.m16n8k16.row.col.f32.f16.f16.f32 "
        "{%0,%1,%2,%3}, {%4,%5,%6,%7}, {%8,%9}, {%0,%1,%2,%3};"
        : "+f"(c[0]), "+f"(c[1]), "+f"(c[2]), "+f"(c[3])
        : "r"(a[0]), "r"(a[1]), "r"(a[2]), "r"(a[3]), "r"(b0), "r"(b1));
}
__device__ __forceinline__ void cvt_split(float4 v, uint2& hi, uint2& lo) {
    __nv_bfloat162 h01 = __floats2bfloat162_rn(v.x, v.y);
    __nv_bfloat162 h23 = __floats2bfloat162_rn(v.z, v.w);
    float rx = v.x - __bfloat162float(h01.x);
    float ry = v.y - __bfloat162float(h01.y);
    float rz = v.z - __bfloat162float(h23.x);
    float rw = v.w - __bfloat162float(h23.y);
    __nv_bfloat162 l01 = __floats2bfloat162_rn(rx, ry);
    __nv_bfloat162 l23 = __floats2bfloat162_rn(rz, rw);
    hi = make_uint2(*reinterpret_cast<uint32_t*>(&h01), *reinterpret_cast<uint32_t*>(&h23));
    lo = make_uint2(*reinterpret_cast<uint32_t*>(&l01), *reinterpret_cast<uint32_t*>(&l23));
}
__device__ __forceinline__ float ex2f(float x) {
    float y;
    asm("ex2.approx.ftz.f32 %0, %1;" : "=f"(y) : "f"(x));
    return y;
}
__device__ __forceinline__ uint32_t pack_f16(float a, float b) {
    __half2 h = __floats2half2_rn(a, b);
    return *reinterpret_cast<uint32_t*>(&h);
}
__device__ __forceinline__ void cp_async16(uint32_t dst, const void* src) {
    asm volatile("cp.async.ca.shared.global [%0], [%1], 16;" :: "r"(dst), "l"(src));
}

// ---------------- pre-pass: K/V and Q -> converted swizzled tiles ----------------
// One 16B chunk per thread (R13 version: max warp-level parallelism).
__global__ __launch_bounds__(256)
void kv_prepass(const float* __restrict__ Q, const float* __restrict__ K,
                const float* __restrict__ V)
{
    int i = blockIdx.x * 256 + threadIdx.x;
    int b   = i >> 16;
    int rem = i & 65535;
    int rg  = rem >> 5;
    int c4  = rem & 31;

    size_t src = ((size_t)b * SEQ + rg) * DIM + c4 * 4;
    uint2 hi, lo;

    // K/V: 64-row tiles
    {
        int kt = rg >> 6, r = rg & 63;
        float4 kv = *(const float4*)(K + src);
        float4 vv = *(const float4*)(V + src);
        unsigned char* dst = g_kv + (size_t)(b * KTILES + kt) * KV_TILE_BYTES;
        uint32_t so = swz(r, c4);
        cvt_split(kv, hi, lo);
        *(uint2*)(dst + 0     + so) = hi;
        *(uint2*)(dst + 16384 + so) = lo;
        uint2 vf;
        vf.x = pack_f16(vv.x, vv.y);
        vf.y = pack_f16(vv.z, vv.w);
        *(uint2*)(dst + OFF_V + so) = vf;
    }
    // Q: 128-row tiles
    {
        int qt = rg >> 7, r = rg & 127;
        float4 qv = *(const float4*)(Q + src);
        unsigned char* dst = g_qc + (size_t)(b * QT_PER + qt) * 65536;
        uint32_t so = swz(r, c4);
        cvt_split(qv, hi, lo);
        *(uint2*)(dst + so)         = hi;
        *(uint2*)(dst + 32768 + so) = lo;
    }
}

// ---------------- main kernel: one CTA = (b, qt, split of 8 ktiles) ----------------
__global__ __launch_bounds__(NTHREADS, 1)
void attn_mma_kernel(const float* __restrict__ scale)
{
    extern __shared__ char smem[];
    const uint32_t sb = smem_u32(smem);

    const int tid  = threadIdx.x;
    const int wid  = tid >> 5;
    const int lane = tid & 31;
    const int g    = lane >> 2;
    const int t4   = lane & 3;
    const int wr   = wid * 16;
    const int qt   = blockIdx.x >> 2;
    const int split= blockIdx.x & 3;
    const int q0   = qt * BM;
    const int b    = blockIdx.y;
    const int kt0  = split * KT_LOCAL;
    const int m7   = lane & 7;
    const float L2E = 1.4426950408889634f;

    const unsigned char* gkv = g_kv + (size_t)b * KTILES * KV_TILE_BYTES;
    const unsigned char* gq  = g_qc + (size_t)(b * QT_PER + qt) * 65536;

    // ---- prologue: one group = Q blob + K(kt0) + V(kt0) ----
    {
        const unsigned char* kb = gkv + (size_t)kt0 * KV_TILE_BYTES;
        #pragma unroll
        for (int u = 0; u < 16; u++) {
            int idx = tid + u * NTHREADS;
            cp_async16(sb + SM_QHI + idx * 16, gq + idx * 16);
        }
        #pragma unroll
        for (int u = 0; u < 8; u++) {
            int idx = tid + u * NTHREADS;
            cp_async16(sb + SM_K(0) + idx * 16, kb + idx * 16);
        }
        #pragma unroll
        for (int u = 0; u < 4; u++) {
            int idx = tid + u * NTHREADS;
            cp_async16(sb + SM_V(0) + idx * 16, kb + OFF_V + idx * 16);
        }
        asm volatile("cp.async.commit_group;" ::: "memory");
    }

    const uint32_t hcA = (lane >> 4) & 1;
    const uint32_t hcB = (lane >> 3) & 1;
    const uint32_t hcV = (lane >> 4) & 1;
    const uint32_t qrow  = (uint32_t)(wr + m7 + ((lane >> 3) & 1) * 8);
    const uint32_t krowl = (uint32_t)(m7 + ((lane >> 4) & 1) * 8);
    const uint32_t vrowl = (uint32_t)(lane & 15);
    const uint32_t qbase = sb + SM_QHI + qrow * 256;

    const float* sp0 = scale + (size_t)(q0 + wr + g) * SEQ + 2 * t4;
    const float* sp1 = sp0 + 8 * SEQ;

    float o[16][4];
    #pragma unroll
    for (int j = 0; j < 16; j++)
        { o[j][0] = 0.f; o[j][1] = 0.f; o[j][2] = 0.f; o[j][3] = 0.f; }
    float m0 = -1e30f, m1 = -1e30f, l0 = 0.f, l1 = 0.f;

    for (int k = 0; k < KT_LOCAL; k++) {
        const int kt = kt0 + k;
        __syncthreads();   // all warps done with tile k-1 -> its slots reusable

        if (k + 1 < KT_LOCAL) {
            const unsigned char* srcb = gkv + (size_t)(kt + 1) * KV_TILE_BYTES;
            uint32_t kd = sb + SM_K((k + 1) & 1);
            #pragma unroll
            for (int u = 0; u < 8; u++) {
                int idx = tid + u * NTHREADS;
                cp_async16(kd + idx * 16, srcb + idx * 16);
            }
            uint32_t vd = sb + SM_V((k + 1) & 1);
            #pragma unroll
            for (int u = 0; u < 4; u++) {
                int idx = tid + u * NTHREADS;
                cp_async16(vd + idx * 16, srcb + OFF_V + idx * 16);
            }
            asm volatile("cp.async.commit_group;" ::: "memory");
            asm volatile("cp.async.wait_group 1;" ::: "memory");
        } else {
            asm volatile("cp.async.wait_group 0;" ::: "memory");
        }
        __syncthreads();   // tile k staged & visible

        const uint32_t kbase = sb + SM_K(k & 1) + krowl * 256;
        const uint32_t vbase = sb + SM_V(k & 1) + vrowl * 256;

        // scale rows -> regs (L2 hits, hidden under QK), log2e folded
        float2 scA[8], scB[8];
        #pragma unroll
        for (int j = 0; j < 8; j++) {
            float2 a = __ldg((const float2*)(sp0 + (size_t)kt * BN + 8 * j));
            float2 c = __ldg((const float2*)(sp1 + (size_t)kt * BN + 8 * j));
            scA[j] = make_float2(a.x * L2E, a.y * L2E);
            scB[j] = make_float2(c.x * L2E, c.y * L2E);
        }

        // ---- S = Q K^T : bf16 3-product split; half-kc batches ----
        float s[8][4];
        #pragma unroll
        for (int j = 0; j < 8; j++)
            { s[j][0] = 0.f; s[j][1] = 0.f; s[j][2] = 0.f; s[j][3] = 0.f; }

        #pragma unroll
        for (int kc = 0; kc < 8; kc++) {
            uint32_t aoff = ((2u * kc + hcA) ^ m7) << 4;
            uint32_t boff = ((2u * kc + hcB) ^ m7) << 4;
            uint32_t ah[4], al[4];
            ldsm_x4(ah, qbase + aoff);
            ldsm_x4(al, qbase + 32768 + aoff);
            {   // jp0, jp1
                uint32_t bh0[4], bl0[4], bh1[4], bl1[4];
                ldsm_x4(bh0, kbase + boff);
                ldsm_x4(bl0, kbase + 16384 + boff);
                ldsm_x4(bh1, kbase + 4096 + boff);
                ldsm_x4(bl1, kbase + 4096 + 16384 + boff);
                mma_bf16(s[0], ah, bh0[0], bh0[1]);
                mma_bf16(s[1], ah, bh0[2], bh0[3]);
                mma_bf16(s[2], ah, bh1[0], bh1[1]);
                mma_bf16(s[3], ah, bh1[2], bh1[3]);
                mma_bf16(s[0], ah, bl0[0], bl0[1]);
                mma_bf16(s[1], ah, bl0[2], bl0[3]);
                mma_bf16(s[2], ah, bl1[0], bl1[1]);
                mma_bf16(s[3], ah, bl1[2], bl1[3]);
                mma_bf16(s[0], al, bh0[0], bh0[1]);
                mma_bf16(s[1], al, bh0[2], bh0[3]);
                mma_bf16(s[2], al, bh1[0], bh1[1]);
                mma_bf16(s[3], al, bh1[2], bh1[3]);
            }
            {   // jp2, jp3
                uint32_t bh2[4], bl2[4], bh3[4], bl3[4];
                ldsm_x4(bh2, kbase + 2 * 4096 + boff);
                ldsm_x4(bl2, kbase + 2 * 4096 + 16384 + boff);
                ldsm_x4(bh3, kbase + 3 * 4096 + boff);
                ldsm_x4(bl3, kbase + 3 * 4096 + 16384 + boff);
                mma_bf16(s[4], ah, bh2[0], bh2[1]);
                mma_bf16(s[5], ah, bh2[2], bh2[3]);
                mma_bf16(s[6], ah, bh3[0], bh3[1]);
                mma_bf16(s[7], ah, bh3[2], bh3[3]);
                mma_bf16(s[4], ah, bl2[0], bl2[1]);
                mma_bf16(s[5], ah, bl2[2], bl2[3]);
                mma_bf16(s[6], ah, bl3[0], bl3[1]);
                mma_bf16(s[7], ah, bl3[2], bl3[3]);
                mma_bf16(s[4], al, bh2[0], bh2[1]);
                mma_bf16(s[5], al, bh2[2], bh2[3]);
                mma_bf16(s[6], al, bh3[0], bh3[1]);
                mma_bf16(s[7], al, bh3[2], bh3[3]);
            }
        }

        // ---- softmax: scale (log2 domain) + row max + alpha + rescale ----
        float mx0 = -1e30f, mx1 = -1e30f;
        #pragma unroll
        for (int j = 0; j < 8; j++) {
            s[j][0] *= scA[j].x; s[j][1] *= scA[j].y;
            s[j][2] *= scB[j].x; s[j][3] *= scB[j].y;
            mx0 = fmaxf(mx0, fmaxf(s[j][0], s[j][1]));
            mx1 = fmaxf(mx1, fmaxf(s[j][2], s[j][3]));
        }
        mx0 = fmaxf(mx0, __shfl_xor_sync(0xffffffffu, mx0, 1));
        mx0 = fmaxf(mx0, __shfl_xor_sync(0xffffffffu, mx0, 2));
        mx1 = fmaxf(mx1, __shfl_xor_sync(0xffffffffu, mx1, 1));
        mx1 = fmaxf(mx1, __shfl_xor_sync(0xffffffffu, mx1, 2));

        float mn0 = fmaxf(m0, mx0), mn1 = fmaxf(m1, mx1);
        float a0 = ex2f(m0 - mn0),  a1 = ex2f(m1 - mn1);
        m0 = mn0; m1 = mn1;
        if (a0 != 1.0f || a1 != 1.0f) {
            l0 *= a0; l1 *= a1;
            #pragma unroll
            for (int j = 0; j < 16; j++) {
                o[j][0] *= a0; o[j][1] *= a0;
                o[j][2] *= a1; o[j][3] *= a1;
            }
        }

        // ---- exp + pack + PV per key-chunk ----
        float sum0 = 0.f, sum1 = 0.f;
        #pragma unroll
        for (int c = 0; c < 4; c++) {
            float e00 = ex2f(s[2*c][0]   - mn0), e01 = ex2f(s[2*c][1]   - mn0);
            float e02 = ex2f(s[2*c][2]   - mn1), e03 = ex2f(s[2*c][3]   - mn1);
            float e10 = ex2f(s[2*c+1][0] - mn0), e11 = ex2f(s[2*c+1][1] - mn0);
            float e12 = ex2f(s[2*c+1][2] - mn1), e13 = ex2f(s[2*c+1][3] - mn1);
            sum0 += e00 + e01 + e10 + e11;
            sum1 += e02 + e03 + e12 + e13;
            uint32_t ph[4];
            ph[0] = pack_f16(e00, e01);
            ph[1] = pack_f16(e02, e03);
            ph[2] = pack_f16(e10, e11);
            ph[3] = pack_f16(e12, e13);
            #pragma unroll
            for (int half = 0; half < 2; half++) {
                uint32_t vh[4][4];
                #pragma unroll
                for (int q = 0; q < 4; q++) {
                    int jp = 4 * half + q;
                    uint32_t va = vbase + c * 4096u + (((2u * jp + hcV) ^ m7) << 4);
                    ldsm_x4_t(vh[q], va);
                }
                #pragma unroll
                for (int q = 0; q < 4; q++) {
                    int jp = 4 * half + q;
                    mma_f16(o[2*jp],   ph, vh[q][0], vh[q][1]);
                    mma_f16(o[2*jp+1], ph, vh[q][2], vh[q][3]);
                }
            }
        }
        l0 += sum0; l1 += sum1;
    }

    // ---- epilogue: quad-reduce l, write unnormalized partials + (m,l) ----
    l0 += __shfl_xor_sync(0xffffffffu, l0, 1);
    l0 += __shfl_xor_sync(0xffffffffu, l0, 2);
    l1 += __shfl_xor_sync(0xffffffffu, l1, 1);
    l1 += __shfl_xor_sync(0xffffffffu, l1, 2);

    const int p = (b * QT_PER + qt) * SPLITS + split;
    float* po = g_part + (size_t)p * BM * DIM;
    const int row0 = wr + g, row1 = row0 + 8;
    #pragma unroll
    for (int j = 0; j < 16; j++) {
        int col = 8 * j + 2 * t4;
        *(float2*)(po + row0 * DIM + col) = make_float2(o[j][0], o[j][1]);
        *(float2*)(po + row1 * DIM + col) = make_float2(o[j][2], o[j][3]);
    }
    if (t4 == 0) {
        g_ml[p * BM + row0] = make_float2(m0, l0);
        g_ml[p * BM + row1] = make_float2(m1, l1);
    }
}

// ---------------- combine: each CTA merges a 32-row slice of one (b,qt) ----------------
__global__ __launch_bounds__(256)
void combine_kernel(float* __restrict__ Out)
{
    const int bq   = blockIdx.x;             // b*QT_PER + qt
    const int qrt  = blockIdx.y;             // row slice: rows 32*qrt .. 32*qrt+31
    const int tid  = threadIdx.x;
    __shared__ float wsh[SPLITS][32];

    if (tid < 32) {
        int row = qrt * 32 + tid;
        float2 ml[SPLITS];
        float M = -1e30f;
        #pragma unroll
        for (int s = 0; s < SPLITS; s++) {
            ml[s] = g_ml[(bq * SPLITS + s) * BM + row];
            M = fmaxf(M, ml[s].x);
        }
        float w[SPLITS], L = 0.f;
        #pragma unroll
        for (int s = 0; s < SPLITS; s++) {
            w[s] = ex2f(ml[s].x - M);        // m is in log2 domain
            L += ml[s].y * w[s];
        }
        float inv = 1.f / L;
        #pragma unroll
        for (int s = 0; s < SPLITS; s++) wsh[s][tid] = w[s] * inv;
    }
    __syncthreads();

    const int base = qrt * 32 * DIM;         // slice offset in elements
    const float* p0 = g_part + (size_t)bq * SPLITS * BM * DIM + base;
    float* out = Out + (size_t)bq * BM * DIM + base;
    for (int e4 = tid; e4 < 32 * DIM / 4; e4 += 256) {
        int e = e4 * 4;
        int row = e >> 7;                    // local row in slice
        float4 v0 = __ldg((const float4*)(p0 + e));
        float4 v1 = __ldg((const float4*)(p0 + BM * DIM + e));
        float4 v2 = __ldg((const float4*)(p0 + 2 * BM * DIM + e));
        float4 v3 = __ldg((const float4*)(p0 + 3 * BM * DIM + e));
        float w0 = wsh[0][row], w1 = wsh[1][row], w2 = wsh[2][row], w3 = wsh[3][row];
        float4 r;
        r.x = v0.x * w0 + v1.x * w1 + v2.x * w2 + v3.x * w3;
        r.y = v0.y * w0 + v1.y * w1 + v2.y * w2 + v3.y * w3;
        r.z = v0.z * w0 + v1.z * w1 + v2.z * w2 + v3.z * w3;
        r.w = v0.w * w0 + v1.w * w1 + v2.w * w2 + v3.w * w3;
        *(float4*)(out + e) = r;
    }
}

extern "C" void kernel_launch(void* const* d_in, const int* in_sizes, int n_in,
                              void* d_out, int out_size)
{
    const float* Q     = (const float*)d_in[0];
    const float* K     = (const float*)d_in[1];
    const float* V     = (const float*)d_in[2];
    const float* scale = (const float*)d_in[3];
    float* O = (float*)d_out;

    kv_prepass<<<(BATCH * SEQ * 32) / 256, 256>>>(Q, K, V);

    cudaFuncSetAttribute(attn_mma_kernel,
                         cudaFuncAttributeMaxDynamicSharedMemorySize, SM_TOTAL);
    dim3 grid(QT_PER * SPLITS, BATCH);   // 64 x 16 = 1024 CTAs
    attn_mma_kernel<<<grid, NTHREADS, SM_TOTAL>>>(scale);

    dim3 cgrid(BATCH * QT_PER, SPLITS);  // 256 x 4 = 1024 light CTAs
    combine_kernel<<<cgrid, 256>>>(O);
}